// round 2
// baseline (speedup 1.0000x reference)
#include <cuda_runtime.h>
#include <cuda_bf16.h>

// Problem constants (fixed by the reference)
#define NW        4          // N_WINDOWS
#define CCH       32         // N_MASKS
#define MPW       8          // masks per window
#define IMG_H     1024
#define IMG_W     1024
#define HW        (IMG_H * IMG_W)
#define WIN_H     512
#define WIN_W     512
#define SLOT_DIM  64
#define SIM_THRESH 0.1f
#define P_MAX     304        // max candidate pairs (<= 6 adjacencies * 49)

// Scratch (device globals; no runtime allocation allowed)
__device__ unsigned      d_edge_parts[NW][4];   // [window][L,R,T,B] channel bitmasks
__device__ int           d_map[CCH];            // final channel remap
__device__ unsigned char d_ids[HW];             // per-pixel argmax channel

// ---------------------------------------------------------------------------
// K0: zero the edge bitmasks (K1 accumulates via atomicOr).
// ---------------------------------------------------------------------------
__global__ void init_kernel()
{
    if (threadIdx.x < NW * 4)
        ((unsigned*)d_edge_parts)[threadIdx.x] = 0u;
}

// ---------------------------------------------------------------------------
// K1: streaming argmax pass. One block per image row (256 threads x float4).
// Reads all 32 channel planes with evict-first hint, writes packed uint8 ids,
// and accumulates window-edge channel bitmasks as a byproduct.
// ---------------------------------------------------------------------------
__global__ void __launch_bounds__(256) argmax_kernel(
    const float* __restrict__ masks,
    const int* __restrict__ pad_left,
    const int* __restrict__ pad_top)
{
    __shared__ unsigned s_edge[NW * 4];
    __shared__ int s_ys[NW], s_ye[NW], s_xs[NW], s_xe[NW];

    if (threadIdx.x < NW * 4) s_edge[threadIdx.x] = 0u;
    if (threadIdx.x < NW) {
        int pl = pad_left[threadIdx.x], pt = pad_top[threadIdx.x];
        s_ys[threadIdx.x] = max(pt, 0);
        s_ye[threadIdx.x] = min(pt + WIN_H, IMG_H);
        s_xs[threadIdx.x] = max(pl, 0);
        s_xe[threadIdx.x] = min(pl + WIN_W, IMG_W);
    }
    __syncthreads();

    const int y   = blockIdx.x;                       // image row
    const int t   = threadIdx.x;                      // float4 within row
    const int idx = y * (IMG_W / 4) + t;              // float4 index
    const int stride4 = HW / 4;

    const float4* m4 = (const float4*)masks;

    float4 v = __ldcs(&m4[idx]);
    float b0 = v.x, b1 = v.y, b2 = v.z, b3 = v.w;
    int a0 = 0, a1 = 0, a2 = 0, a3 = 0;

    #pragma unroll
    for (int c = 1; c < CCH; c++) {
        float4 q = __ldcs(&m4[(long long)c * stride4 + idx]);
        if (q.x > b0) { b0 = q.x; a0 = c; }
        if (q.y > b1) { b1 = q.y; a1 = c; }
        if (q.z > b2) { b2 = q.z; a2 = c; }
        if (q.w > b3) { b3 = q.w; a3 = c; }
    }

    // write packed ids (warp: 128B contiguous)
    uchar4 pk = make_uchar4((unsigned char)a0, (unsigned char)a1,
                            (unsigned char)a2, (unsigned char)a3);
    *(uchar4*)&d_ids[idx * 4] = pk;

    // edge-flag accumulation (rare-true predicates; shared atomics)
    int ids[4] = {a0, a1, a2, a3};
    #pragma unroll
    for (int w = 0; w < NW; w++) {
        int ys = s_ys[w], ye = s_ye[w], xs = s_xs[w], xe = s_xe[w];
        if (ys >= ye || xs >= xe) continue;
        if (y < ys || y >= ye) continue;
        bool top = (y == ys), bot = (y == ye - 1);
        #pragma unroll
        for (int k = 0; k < 4; k++) {
            int x = t * 4 + k;
            if (x < xs || x >= xe) continue;
            int id = ids[k];
            if ((id >> 3) != w) continue;       // id in [w*8, w*8+8)
            unsigned bit = 1u << id;
            if (x == xs)     atomicOr(&s_edge[w * 4 + 0], bit);
            if (x == xe - 1) atomicOr(&s_edge[w * 4 + 1], bit);
            if (top)         atomicOr(&s_edge[w * 4 + 2], bit);
            if (bot)         atomicOr(&s_edge[w * 4 + 3], bit);
        }
    }
    __syncthreads();
    if (threadIdx.x < NW * 4) {
        unsigned m = s_edge[threadIdx.x];
        if (m) atomicOr(&((unsigned*)d_edge_parts)[threadIdx.x], m);
    }
}

// ---------------------------------------------------------------------------
// K2: one block. Builds adjacency + candidate pair list, computes cosine
// similarities, runs the sequential merge scan, emits the channel remap.
// ---------------------------------------------------------------------------
__global__ void __launch_bounds__(256) map_kernel(
    const float* __restrict__ sf,       // (NW, MPW-1, SLOT_DIM)
    const int* __restrict__ pad_left,
    const int* __restrict__ pad_top)
{
    __shared__ int  s_ci[P_MAX];
    __shared__ int  s_cj[P_MAX];
    __shared__ char s_hz[P_MAX];
    __shared__ char s_pass[P_MAX];
    __shared__ int  s_P;

    if (threadIdx.x == 0) {
        int pl[NW], pt[NW];
        for (int i = 0; i < NW; i++) { pl[i] = pad_left[i]; pt[i] = pad_top[i]; }

        int na = 0;
        int ai[12], aj[12]; char ah[12];
        for (int i = 0; i < NW; i++) {
            for (int j = i + 1; j < NW; j++) {
                if (pt[i] == pt[j] && abs(pl[i] - pl[j]) == WIN_W) {
                    if (pl[i] < pl[j]) { ai[na] = i; aj[na] = j; }
                    else               { ai[na] = j; aj[na] = i; }
                    ah[na] = 1; na++;
                }
                if (pl[i] == pl[j] && abs(pt[i] - pt[j]) == WIN_H) {
                    if (pt[i] < pt[j]) { ai[na] = i; aj[na] = j; }
                    else               { ai[na] = j; aj[na] = i; }
                    ah[na] = 0; na++;
                }
            }
        }
        int P = 0;
        for (int a = 0; a < na; a++) {
            int si = ai[a] * MPW, sj = aj[a] * MPW;
            for (int ci = si + 1; ci < si + MPW; ci++)
                for (int cj = sj + 1; cj < sj + MPW; cj++) {
                    s_ci[P] = ci; s_cj[P] = cj; s_hz[P] = ah[a]; P++;
                }
        }
        s_P = P;
    }
    __syncthreads();

    int P = s_P;
    for (int p = threadIdx.x; p < P; p += blockDim.x) {
        int ci = s_ci[p], cj = s_cj[p];
        int wi = ci / MPW, wj = cj / MPW;
        int ri = ci % MPW - 1, rj = cj % MPW - 1;
        const float* fi = sf + ((long long)wi * (MPW - 1) + ri) * SLOT_DIM;
        const float* fj = sf + ((long long)wj * (MPW - 1) + rj) * SLOT_DIM;
        float dot = 0.f, ni = 0.f, nj = 0.f;
        #pragma unroll
        for (int k = 0; k < SLOT_DIM; k++) {
            float a = fi[k], b = fj[k];
            dot += a * b; ni += a * a; nj += b * b;
        }
        float sim = dot / ((sqrtf(ni) + 1e-8f) * (sqrtf(nj) + 1e-8f));

        bool ok;
        if (s_hz[p]) {
            ok = ((d_edge_parts[wi][1] >> ci) & 1u) && ((d_edge_parts[wj][0] >> cj) & 1u);
        } else {
            ok = ((d_edge_parts[wi][3] >> ci) & 1u) && ((d_edge_parts[wj][2] >> cj) & 1u);
        }
        s_pass[p] = (ok && sim > SIM_THRESH) ? 1 : 0;
    }
    __syncthreads();

    if (threadIdx.x == 0) {
        int mp[CCH];
        bool merged[CCH];
        for (int c = 0; c < CCH; c++) { mp[c] = c; merged[c] = false; }
        for (int p = 0; p < P; p++) {
            int ci = s_ci[p], cj = s_cj[p];
            if (s_pass[p] && !merged[ci] && !merged[cj]) {
                int keep = min(ci, cj), rem = max(ci, cj);
                for (int c = 0; c < CCH; c++)
                    if (mp[c] == rem) mp[c] = keep;
                merged[rem] = true;
            }
        }
        for (int c = 0; c < CCH; c++) d_map[c] = mp[c];
    }
}

// ---------------------------------------------------------------------------
// K3: scatter pass. Read packed ids (4B/thread), write remapped one-hot for
// all 32 planes with streaming (evict-first) stores. Pure write stream.
// ---------------------------------------------------------------------------
__global__ void __launch_bounds__(256) scatter_kernel(
    float* __restrict__ out)
{
    __shared__ int smap[CCH];
    if (threadIdx.x < CCH) smap[threadIdx.x] = d_map[threadIdx.x];
    __syncthreads();

    const int idx = blockIdx.x * 256 + threadIdx.x;   // float4 index
    const int stride4 = HW / 4;

    uchar4 pk = *(const uchar4*)&d_ids[idx * 4];
    int a0 = smap[pk.x], a1 = smap[pk.y], a2 = smap[pk.z], a3 = smap[pk.w];

    float4* o4 = (float4*)out;
    #pragma unroll
    for (int c = 0; c < CCH; c++) {
        float4 o;
        o.x = (a0 == c) ? 1.0f : 0.0f;
        o.y = (a1 == c) ? 1.0f : 0.0f;
        o.z = (a2 == c) ? 1.0f : 0.0f;
        o.w = (a3 == c) ? 1.0f : 0.0f;
        __stcs(&o4[(long long)c * stride4 + idx], o);
    }
}

// ---------------------------------------------------------------------------
extern "C" void kernel_launch(void* const* d_in, const int* in_sizes, int n_in,
                              void* d_out, int out_size)
{
    const float* masks = (const float*)d_in[0];
    const float* sf    = (const float*)d_in[1];
    const int*   pl    = (const int*)d_in[2];
    const int*   pt    = (const int*)d_in[3];
    float*       out   = (float*)d_out;

    init_kernel<<<1, 32>>>();
    argmax_kernel<<<IMG_H, 256>>>(masks, pl, pt);
    map_kernel<<<1, 256>>>(sf, pl, pt);
    scatter_kernel<<<HW / 4 / 256, 256>>>(out);
}

// round 3
// speedup vs baseline: 1.3723x; 1.3723x over previous
#include <cuda_runtime.h>
#include <cuda_bf16.h>
#include <cstdint>

// Problem constants (fixed by the reference)
#define NW        4          // N_WINDOWS
#define CCH       32         // N_MASKS
#define MPW       8          // masks per window
#define IMG_H     1024
#define IMG_W     1024
#define HW        (IMG_H * IMG_W)
#define WIN_H     512
#define WIN_W     512
#define SLOT_DIM  64
#define SIM_THRESH 0.1f
#define P_MAX     304

#define CHUNK     2048       // pixels per block in main kernel
#define GROUPS    2          // 1024 px per group (256 float4)

// Scratch (device globals; no runtime allocation allowed)
__device__ unsigned d_edge_q[NW][4][4];   // [window][edge L,R,T,B][quarter] bitmasks
__device__ int      d_map[CCH];           // final channel remap

__device__ __forceinline__ uint32_t smem_u32(const void* p) {
    return (uint32_t)__cvta_generic_to_shared(p);
}

// ---------------------------------------------------------------------------
// K1: edge flags. 64 blocks: (window, edge, quarter). Each thread handles one
// edge pixel: argmax over 32 planes; set channel bit if argmax is in-window.
// Each block writes its own quarter word unconditionally -> no init, no atomics.
// ---------------------------------------------------------------------------
__global__ void __launch_bounds__(128) edge_kernel(
    const float* __restrict__ masks,
    const int* __restrict__ pad_left,
    const int* __restrict__ pad_top)
{
    int q  = blockIdx.x & 3;
    int we = blockIdx.x >> 2;
    int w  = we >> 2;
    int e  = we & 3;            // 0=L 1=R 2=T 3=B

    int pl = pad_left[w], pt = pad_top[w];
    int ys = max(pt, 0), ye = min(pt + WIN_H, IMG_H);
    int xs = max(pl, 0), xe = min(pl + WIN_W, IMG_W);

    unsigned mybit = 0u;
    if (ys < ye && xs < xe) {
        int len = (e < 2) ? (ye - ys) : (xe - xs);
        int k = q * 128 + threadIdx.x;
        if (k < len) {
            int y, x;
            if      (e == 0) { y = ys + k; x = xs;     }
            else if (e == 1) { y = ys + k; x = xe - 1; }
            else if (e == 2) { y = ys;     x = xs + k; }
            else             { y = ye - 1; x = xs + k; }
            const float* p = masks + (long long)y * IMG_W + x;
            float best = __ldg(p);
            int id = 0;
            #pragma unroll
            for (int c = 1; c < CCH; c++) {
                float v = __ldg(p + (long long)c * HW);
                if (v > best) { best = v; id = c; }
            }
            if ((id >> 3) == w) mybit = 1u << id;
        }
    }

    unsigned wm = __reduce_or_sync(0xffffffffu, mybit);
    __shared__ unsigned sm[4];
    if ((threadIdx.x & 31) == 0) sm[threadIdx.x >> 5] = wm;
    __syncthreads();
    if (threadIdx.x == 0)
        d_edge_q[w][e][q] = sm[0] | sm[1] | sm[2] | sm[3];
}

// ---------------------------------------------------------------------------
// K2: one block. Builds adjacency + candidate pairs, cosine sims, sequential
// merge scan -> 32-entry channel remap table.
// ---------------------------------------------------------------------------
__global__ void __launch_bounds__(256) map_kernel(
    const float* __restrict__ sf,
    const int* __restrict__ pad_left,
    const int* __restrict__ pad_top)
{
    __shared__ int  s_ci[P_MAX];
    __shared__ int  s_cj[P_MAX];
    __shared__ char s_hz[P_MAX];
    __shared__ char s_pass[P_MAX];
    __shared__ int  s_P;
    __shared__ unsigned s_edge[NW][4];

    if (threadIdx.x < NW * 4) {
        int w = threadIdx.x >> 2, e = threadIdx.x & 3;
        s_edge[w][e] = d_edge_q[w][e][0] | d_edge_q[w][e][1] |
                       d_edge_q[w][e][2] | d_edge_q[w][e][3];
    }

    if (threadIdx.x == 0) {
        int pl[NW], pt[NW];
        for (int i = 0; i < NW; i++) { pl[i] = pad_left[i]; pt[i] = pad_top[i]; }

        int na = 0;
        int ai[12], aj[12]; char ah[12];
        for (int i = 0; i < NW; i++) {
            for (int j = i + 1; j < NW; j++) {
                if (pt[i] == pt[j] && abs(pl[i] - pl[j]) == WIN_W) {
                    if (pl[i] < pl[j]) { ai[na] = i; aj[na] = j; }
                    else               { ai[na] = j; aj[na] = i; }
                    ah[na] = 1; na++;
                }
                if (pl[i] == pl[j] && abs(pt[i] - pt[j]) == WIN_H) {
                    if (pt[i] < pt[j]) { ai[na] = i; aj[na] = j; }
                    else               { ai[na] = j; aj[na] = i; }
                    ah[na] = 0; na++;
                }
            }
        }
        int P = 0;
        for (int a = 0; a < na; a++) {
            int si = ai[a] * MPW, sj = aj[a] * MPW;
            for (int ci = si + 1; ci < si + MPW; ci++)
                for (int cj = sj + 1; cj < sj + MPW; cj++) {
                    s_ci[P] = ci; s_cj[P] = cj; s_hz[P] = ah[a]; P++;
                }
        }
        s_P = P;
    }
    __syncthreads();

    int P = s_P;
    for (int p = threadIdx.x; p < P; p += blockDim.x) {
        int ci = s_ci[p], cj = s_cj[p];
        int wi = ci / MPW, wj = cj / MPW;
        int ri = ci % MPW - 1, rj = cj % MPW - 1;
        const float* fi = sf + ((long long)wi * (MPW - 1) + ri) * SLOT_DIM;
        const float* fj = sf + ((long long)wj * (MPW - 1) + rj) * SLOT_DIM;
        float dot = 0.f, ni = 0.f, nj = 0.f;
        #pragma unroll
        for (int k = 0; k < SLOT_DIM; k++) {
            float a = fi[k], b = fj[k];
            dot += a * b; ni += a * a; nj += b * b;
        }
        float sim = dot / ((sqrtf(ni) + 1e-8f) * (sqrtf(nj) + 1e-8f));

        bool ok;
        if (s_hz[p]) {
            ok = ((s_edge[wi][1] >> ci) & 1u) && ((s_edge[wj][0] >> cj) & 1u);
        } else {
            ok = ((s_edge[wi][3] >> ci) & 1u) && ((s_edge[wj][2] >> cj) & 1u);
        }
        s_pass[p] = (ok && sim > SIM_THRESH) ? 1 : 0;
    }
    __syncthreads();

    if (threadIdx.x == 0) {
        int mp[CCH];
        bool merged[CCH];
        for (int c = 0; c < CCH; c++) { mp[c] = c; merged[c] = false; }
        for (int p = 0; p < P; p++) {
            int ci = s_ci[p], cj = s_cj[p];
            if (s_pass[p] && !merged[ci] && !merged[cj]) {
                int keep = min(ci, cj), rem = max(ci, cj);
                for (int c = 0; c < CCH; c++)
                    if (mp[c] == rem) mp[c] = keep;
                merged[rem] = true;
            }
        }
        for (int c = 0; c < CCH; c++) d_map[c] = mp[c];
    }
}

// ---------------------------------------------------------------------------
// K3: fused main pass. Each block owns CHUNK=2048 px. Reads all 32 planes
// (LDG.128, evict-first), per-pixel argmax + remap, then per channel stages
// the one-hot tile in SMEM and drains it with an 8KB cp.async.bulk store
// (double-buffered) -> no per-thread STG path, large contiguous DRAM writes.
// ---------------------------------------------------------------------------
__global__ void __launch_bounds__(256) main_kernel(
    const float* __restrict__ masks,
    float* __restrict__ out)
{
    __shared__ __align__(16) float sbuf[2][CHUNK];
    __shared__ int smap[CCH];
    if (threadIdx.x < CCH) smap[threadIdx.x] = d_map[threadIdx.x];
    __syncthreads();

    const int t = threadIdx.x;
    const int base4 = blockIdx.x * (CHUNK / 4);     // float4 index of chunk start
    const int stride4 = HW / 4;
    const float4* m4 = (const float4*)masks;

    int ids[GROUPS][4];
    #pragma unroll
    for (int g = 0; g < GROUPS; g++) {
        int idx = base4 + g * 256 + t;
        float4 v = __ldcs(&m4[idx]);
        float b0 = v.x, b1 = v.y, b2 = v.z, b3 = v.w;
        int a0 = 0, a1 = 0, a2 = 0, a3 = 0;
        #pragma unroll
        for (int c = 1; c < CCH; c++) {
            float4 q = __ldcs(&m4[(long long)c * stride4 + idx]);
            if (q.x > b0) { b0 = q.x; a0 = c; }
            if (q.y > b1) { b1 = q.y; a1 = c; }
            if (q.z > b2) { b2 = q.z; a2 = c; }
            if (q.w > b3) { b3 = q.w; a3 = c; }
        }
        ids[g][0] = smap[a0]; ids[g][1] = smap[a1];
        ids[g][2] = smap[a2]; ids[g][3] = smap[a3];
    }

    // staged one-hot writes, double buffered
    for (int c = 0; c < CCH; c++) {
        int buf = c & 1;
        if (c >= 2) {
            if (t == 0)
                asm volatile("cp.async.bulk.wait_group.read 1;" ::: "memory");
            __syncthreads();    // buffer `buf` free for refill
        }
        float4* sb4 = (float4*)sbuf[buf];
        #pragma unroll
        for (int g = 0; g < GROUPS; g++) {
            float4 o;
            o.x = (ids[g][0] == c) ? 1.0f : 0.0f;
            o.y = (ids[g][1] == c) ? 1.0f : 0.0f;
            o.z = (ids[g][2] == c) ? 1.0f : 0.0f;
            o.w = (ids[g][3] == c) ? 1.0f : 0.0f;
            sb4[g * 256 + t] = o;
        }
        __syncthreads();        // all STS done
        if (t == 0) {
            float* gdst = out + (long long)c * HW + (long long)blockIdx.x * CHUNK;
            uint32_t saddr = smem_u32(sbuf[buf]);
            asm volatile("fence.proxy.async.shared::cta;" ::: "memory");
            asm volatile(
                "cp.async.bulk.global.shared::cta.bulk_group [%0], [%1], %2;"
                :: "l"(gdst), "r"(saddr), "n"(CHUNK * 4) : "memory");
            asm volatile("cp.async.bulk.commit_group;" ::: "memory");
        }
    }
    // drain pending bulk reads from SMEM before block exit
    if (t == 0)
        asm volatile("cp.async.bulk.wait_group.read 0;" ::: "memory");
    __syncthreads();
}

// ---------------------------------------------------------------------------
extern "C" void kernel_launch(void* const* d_in, const int* in_sizes, int n_in,
                              void* d_out, int out_size)
{
    const float* masks = (const float*)d_in[0];
    const float* sf    = (const float*)d_in[1];
    const int*   pl    = (const int*)d_in[2];
    const int*   pt    = (const int*)d_in[3];
    float*       out   = (float*)d_out;

    edge_kernel<<<NW * 4 * 4, 128>>>(masks, pl, pt);
    map_kernel<<<1, 256>>>(sf, pl, pt);
    main_kernel<<<HW / CHUNK, 256>>>(masks, out);
}